// round 6
// baseline (speedup 1.0000x reference)
#include <cuda_runtime.h>
#include <cuda_bf16.h>

#define SS   2048
#define BB   64
#define HH   8
#define KK   12
#define NPOS 11

// Scratch (no allocations allowed)
__device__ unsigned int   d_bits[HH * 128];     // head_table packed bitsets
__device__ unsigned short d_addrv[SS * BB];     // value-table addresses per (s,b)
__device__ __align__(16) unsigned short d_aq[SS * HH];
__device__ __align__(16) unsigned short d_ak[SS * HH];
__device__ __align__(16) unsigned short d_ap[SS * HH];

// ---------------------------------------------------------------------------
// Kernel 1: precompute everything. Grid = 512 blocks x 256 threads.
// ---------------------------------------------------------------------------
__global__ void prep_kernel(const int* __restrict__ tokens,
                            const int* __restrict__ conn_heads,
                            const float* __restrict__ head_table,
                            const int* __restrict__ conn_v) {
    __shared__ int sconn_v[BB * KK];
    __shared__ int sconn_h[HH * KK];
    __shared__ unsigned long long stok[4];

    int tid  = threadIdx.x;
    int warp = tid >> 5, lane = tid & 31;

    if (blockIdx.x < 128) {
        int t = blockIdx.x * 8 + warp;
        unsigned m = __ballot_sync(0xffffffffu, head_table[t * 32 + lane] != 0.0f);
        if (lane == 0) d_bits[t] = m;
    }

    int s0 = blockIdx.x * 4;
    if (warp < 4) {
        const int* trow = tokens + (s0 + warp) * BB;
        unsigned lo = __ballot_sync(0xffffffffu, trow[lane] != 0);
        unsigned hi = __ballot_sync(0xffffffffu, trow[lane + 32] != 0);
        if (lane == 0)
            stok[warp] = (unsigned long long)lo | ((unsigned long long)hi << 32);
    }
    for (int i = tid; i < BB * KK; i += 256) sconn_v[i] = conn_v[i];
    if (tid < HH * KK) sconn_h[tid] = conn_heads[tid];
    __syncthreads();

    {
        int sl = tid >> 6, b = tid & 63;
        unsigned long long tok = stok[sl];
        int a = 0;
#pragma unroll
        for (int j = 0; j < KK; j++) {
            int c = sconn_v[b * KK + j];
            a |= (int)((tok >> c) & 1ull) << (KK - 1 - j);
        }
        d_addrv[(s0 + sl) * BB + b] = (unsigned short)a;
    }

    if (tid < 32) {
        int sl = tid >> 3, h = tid & 7;
        int s = s0 + sl;
        unsigned long long tok = stok[sl];
        int aq = 0, ak = 0, ap = 0;
#pragma unroll
        for (int j = 0; j < KK; j++) {
            int c  = sconn_h[h * KK + j];
            int p2 = 1 << (KK - 1 - j);
            if (c < BB)            aq |= (int)((tok >> c) & 1ull) * p2;
            else if (c < 2 * BB)   ak |= (int)((tok >> (c - BB)) & 1ull) * p2;
            else                   ap |= ((s >> (NPOS - 1 - (c - 2 * BB))) & 1) * p2;
        }
        d_aq[s * HH + h] = (unsigned short)aq;
        d_ak[s * HH + h] = (unsigned short)ak;
        d_ap[s * HH + h] = (unsigned short)ap;
    }
}

// ---------------------------------------------------------------------------
#define PROBE(h, a) ((sbits[((h) << 7) + ((a) >> 5)] >> ((a) & 31)) & 1u)

// AND of heads 0..3 (uses kk.x/.y, pp.x/.y)
__device__ __forceinline__ unsigned and4_lo(const unsigned* sbits, uint4 kk, uint4 pp,
                                            int q0, int q1, int q2, int q3) {
    int a0 = q0 + (kk.x & 0xffff) + (pp.x & 0xffff);
    int a1 = q1 + (kk.x >> 16)    + (pp.x >> 16);
    int a2 = q2 + (kk.y & 0xffff) + (pp.y & 0xffff);
    int a3 = q3 + (kk.y >> 16)    + (pp.y >> 16);
    return PROBE(0, a0) & PROBE(1, a1) & PROBE(2, a2) & PROBE(3, a3);
}
// AND of heads 4..7 (uses kk.z/.w, pp.z/.w)
__device__ __forceinline__ unsigned and4_hi(const unsigned* sbits, uint4 kk, uint4 pp,
                                            int q4, int q5, int q6, int q7) {
    int a4 = q4 + (kk.z & 0xffff) + (pp.z & 0xffff);
    int a5 = q5 + (kk.z >> 16)    + (pp.z >> 16);
    int a6 = q6 + (kk.w & 0xffff) + (pp.w & 0xffff);
    int a7 = q7 + (kk.w >> 16)    + (pp.w >> 16);
    return PROBE(4, a4) & PROBE(5, a5) & PROBE(6, a6) & PROBE(7, a7);
}
// full vote count (Phase B only)
__device__ __forceinline__ int votes8(const unsigned* sbits, uint4 kk, uint4 pp,
                                      int q0, int q1, int q2, int q3,
                                      int q4, int q5, int q6, int q7) {
    int a0 = q0 + (kk.x & 0xffff) + (pp.x & 0xffff);
    int a1 = q1 + (kk.x >> 16)    + (pp.x >> 16);
    int a2 = q2 + (kk.y & 0xffff) + (pp.y & 0xffff);
    int a3 = q3 + (kk.y >> 16)    + (pp.y >> 16);
    int a4 = q4 + (kk.z & 0xffff) + (pp.z & 0xffff);
    int a5 = q5 + (kk.z >> 16)    + (pp.z >> 16);
    int a6 = q6 + (kk.w & 0xffff) + (pp.w & 0xffff);
    int a7 = q7 + (kk.w >> 16)    + (pp.w >> 16);
    return (int)(PROBE(0, a0) + PROBE(1, a1) + PROBE(2, a2) + PROBE(3, a3) +
                 PROBE(4, a4) + PROBE(5, a5) + PROBE(6, a6) + PROBE(7, a7));
}

// ---------------------------------------------------------------------------
// Kernel 2: block-per-row. 2048 blocks x 128 threads.
// Phase A: find FIRST column with all-8 votes (AND test, short-circuited at
//          4 heads); 512 cols/iter (4/thread). Non-8 votes are irrelevant
//          when an 8 exists (8 is the ceiling, argmax = first 8).
// Phase B: (rare: no 8 in entire row) full vote-count argmax.
// ---------------------------------------------------------------------------
__global__ void __launch_bounds__(128) scan_kernel(const float* __restrict__ table_v,
                                                   float* __restrict__ out) {
    __shared__ unsigned int sbits[HH * 128];
    __shared__ unsigned int wm[4][4];     // [group][warp]
    __shared__ int skey[4];

    int tid  = threadIdx.x;
    int warp = tid >> 5, lane = tid & 31;
    int row  = blockIdx.x;

    for (int i = tid; i < HH * 128; i += 128) sbits[i] = d_bits[i];
    __syncthreads();

    uint4 qq = ((const uint4*)d_aq)[row];
    int q0 = qq.x & 0xffff, q1 = qq.x >> 16;
    int q2 = qq.y & 0xffff, q3 = qq.y >> 16;
    int q4 = qq.z & 0xffff, q5 = qq.z >> 16;
    int q6 = qq.w & 0xffff, q7 = qq.w >> 16;

    const uint4* ak4 = (const uint4*)d_ak;
    const uint4* ap4 = (const uint4*)d_ap;

    int best_v = -1, best_j = 0;
    bool found8 = false;

    // -------- Phase A: first all-8 column --------
    for (int base = 0; base <= row; base += 512) {
        uint4 kk[4], pp[4];
        bool  in[4];
        unsigned f[4];
#pragma unroll
        for (int c = 0; c < 4; c++) {
            int j = base + (c << 7) + tid;
            in[c] = (j <= row);
            if (in[c]) { kk[c] = ak4[j]; pp[c] = ap4[row - j]; }
        }
#pragma unroll
        for (int c = 0; c < 4; c++) {
            unsigned b = 0;
            if (in[c]) {
                b = and4_lo(sbits, kk[c], pp[c], q0, q1, q2, q3);
                if (b) b = and4_hi(sbits, kk[c], pp[c], q4, q5, q6, q7);
            }
            f[c] = b;
        }
        if (__syncthreads_or(f[0] | f[1] | f[2] | f[3])) {
#pragma unroll
            for (int c = 0; c < 4; c++) {
                unsigned m = __ballot_sync(0xffffffffu, f[c]);
                if (lane == 0) wm[c][warp] = m;
            }
            __syncthreads();
            int bj = -1;
#pragma unroll
            for (int g = 0; g < 4; g++)
#pragma unroll
                for (int w = 0; w < 4; w++)
                    if (bj < 0 && wm[g][w])
                        bj = base + (g << 7) + (w << 5) + (__ffs(wm[g][w]) - 1);
            best_v = HH;
            best_j = bj;
            found8 = true;
            break;
        }
    }

    // -------- Phase B: rare full argmax (no 8 anywhere in the row) --------
    if (!found8) {
        for (int base = 0; base <= row; base += 512) {
#pragma unroll
            for (int c = 0; c < 4; c++) {
                int j = base + (c << 7) + tid;
                if (j <= row) {
                    uint4 kk = ak4[j];
                    uint4 pp = ap4[row - j];
                    int v = votes8(sbits, kk, pp, q0, q1, q2, q3, q4, q5, q6, q7);
                    if (v > best_v) { best_v = v; best_j = j; }  // ascending j
                }
            }
        }
        int key = (best_v << 11) | (2047 - best_j);
        key = __reduce_max_sync(0xffffffffu, key);
        if (lane == 0) skey[warp] = key;
        __syncthreads();
        key = max(max(skey[0], skey[1]), max(skey[2], skey[3]));
        best_v = key >> 11;
        best_j = 2047 - (key & 2047);
    }

    // -------- Output row (threads 0..63), block-uniform (best_v, best_j) ----
    if (tid < BB) {
        float r = 0.0f;
        if (best_v > 0) {
            int a = d_addrv[best_j * BB + tid];
            r = table_v[tid * 4096 + a];
        }
        out[row * BB + tid] = r;
    }
}

// ---------------------------------------------------------------------------
extern "C" void kernel_launch(void* const* d_in, const int* in_sizes, int n_in,
                              void* d_out, int out_size) {
    const int*   tokens     = (const int*)d_in[0];
    const int*   conn_heads = (const int*)d_in[1];
    const float* head_table = (const float*)d_in[2];
    const int*   conn_v     = (const int*)d_in[3];
    const float* table_v    = (const float*)d_in[4];
    float*       out        = (float*)d_out;

    prep_kernel<<<512, 256>>>(tokens, conn_heads, head_table, conn_v);
    scan_kernel<<<SS, 128>>>(table_v, out);
}

// round 7
// speedup vs baseline: 1.4611x; 1.4611x over previous
#include <cuda_runtime.h>
#include <cuda_bf16.h>

#define SS   2048
#define BB   64
#define HH   8
#define KK   12
#define NPOS 11

// Scratch (no allocations allowed)
__device__ unsigned int   d_bits[HH * 128];     // head_table packed bitsets
__device__ unsigned short d_addrv[SS * BB];     // value-table addresses per (s,b)
__device__ __align__(16) unsigned short d_aq[SS * HH];
__device__ __align__(16) unsigned short d_ak[SS * HH];
__device__ __align__(16) unsigned short d_ap[SS * HH];

// ---------------------------------------------------------------------------
// Kernel 1: precompute everything. Grid = 512 blocks x 256 threads.
// ---------------------------------------------------------------------------
__global__ void prep_kernel(const int* __restrict__ tokens,
                            const int* __restrict__ conn_heads,
                            const float* __restrict__ head_table,
                            const int* __restrict__ conn_v) {
    __shared__ int sconn_v[BB * KK];
    __shared__ int sconn_h[HH * KK];
    __shared__ unsigned long long stok[4];

    int tid  = threadIdx.x;
    int warp = tid >> 5, lane = tid & 31;

    if (blockIdx.x < 128) {
        int t = blockIdx.x * 8 + warp;
        unsigned m = __ballot_sync(0xffffffffu, head_table[t * 32 + lane] != 0.0f);
        if (lane == 0) d_bits[t] = m;
    }

    int s0 = blockIdx.x * 4;
    if (warp < 4) {
        const int* trow = tokens + (s0 + warp) * BB;
        unsigned lo = __ballot_sync(0xffffffffu, trow[lane] != 0);
        unsigned hi = __ballot_sync(0xffffffffu, trow[lane + 32] != 0);
        if (lane == 0)
            stok[warp] = (unsigned long long)lo | ((unsigned long long)hi << 32);
    }
    for (int i = tid; i < BB * KK; i += 256) sconn_v[i] = conn_v[i];
    if (tid < HH * KK) sconn_h[tid] = conn_heads[tid];
    __syncthreads();

    {
        int sl = tid >> 6, b = tid & 63;
        unsigned long long tok = stok[sl];
        int a = 0;
#pragma unroll
        for (int j = 0; j < KK; j++) {
            int c = sconn_v[b * KK + j];
            a |= (int)((tok >> c) & 1ull) << (KK - 1 - j);
        }
        d_addrv[(s0 + sl) * BB + b] = (unsigned short)a;
    }

    if (tid < 32) {
        int sl = tid >> 3, h = tid & 7;
        int s = s0 + sl;
        unsigned long long tok = stok[sl];
        int aq = 0, ak = 0, ap = 0;
#pragma unroll
        for (int j = 0; j < KK; j++) {
            int c  = sconn_h[h * KK + j];
            int p2 = 1 << (KK - 1 - j);
            if (c < BB)            aq |= (int)((tok >> c) & 1ull) * p2;
            else if (c < 2 * BB)   ak |= (int)((tok >> (c - BB)) & 1ull) * p2;
            else                   ap |= ((s >> (NPOS - 1 - (c - 2 * BB))) & 1) * p2;
        }
        d_aq[s * HH + h] = (unsigned short)aq;
        d_ak[s * HH + h] = (unsigned short)ak;
        d_ap[s * HH + h] = (unsigned short)ap;
    }
}

// ---------------------------------------------------------------------------
#define PROBE(h, a) ((sbits[((h) << 7) + ((a) >> 5)] >> ((a) & 31)) & 1u)

__device__ __forceinline__ int votes8(const unsigned* sbits, uint4 kk, uint4 pp,
                                      int q0, int q1, int q2, int q3,
                                      int q4, int q5, int q6, int q7) {
    int a0 = q0 + (kk.x & 0xffff) + (pp.x & 0xffff);
    int a1 = q1 + (kk.x >> 16)    + (pp.x >> 16);
    int a2 = q2 + (kk.y & 0xffff) + (pp.y & 0xffff);
    int a3 = q3 + (kk.y >> 16)    + (pp.y >> 16);
    int a4 = q4 + (kk.z & 0xffff) + (pp.z & 0xffff);
    int a5 = q5 + (kk.z >> 16)    + (pp.z >> 16);
    int a6 = q6 + (kk.w & 0xffff) + (pp.w & 0xffff);
    int a7 = q7 + (kk.w >> 16)    + (pp.w >> 16);
    return (int)(PROBE(0, a0) + PROBE(1, a1) + PROBE(2, a2) + PROBE(3, a3) +
                 PROBE(4, a4) + PROBE(5, a5) + PROBE(6, a6) + PROBE(7, a7));
}

// ---------------------------------------------------------------------------
// Kernel 2: block-per-row, WARP-AUTONOMOUS. 2048 blocks x 128 threads.
// Row's n=row+1 columns split into 4 contiguous 64-aligned chunks, one per
// warp. Each warp scans its chunk independently (64 cols/iter, 2/lane),
// warp-ballot early exit at its chunk's first v==8. NO block barrier in the
// loop. One final combine: lowest chunk with an 8 wins; else key-max.
// ---------------------------------------------------------------------------
__global__ void __launch_bounds__(128) scan_kernel(const float* __restrict__ table_v,
                                                   float* __restrict__ out) {
    __shared__ unsigned int sbits[HH * 128];
    __shared__ int sfj[4];     // per-warp first-8 column (or INT_MAX)
    __shared__ int skey[4];    // per-warp packed best key

    int tid  = threadIdx.x;
    int warp = tid >> 5, lane = tid & 31;
    int row  = blockIdx.x;

    for (int i = tid; i < HH * 128; i += 128) sbits[i] = d_bits[i];
    __syncthreads();

    uint4 qq = ((const uint4*)d_aq)[row];
    int q0 = qq.x & 0xffff, q1 = qq.x >> 16;
    int q2 = qq.y & 0xffff, q3 = qq.y >> 16;
    int q4 = qq.z & 0xffff, q5 = qq.z >> 16;
    int q6 = qq.w & 0xffff, q7 = qq.w >> 16;

    const uint4* ak4 = (const uint4*)d_ak;
    const uint4* ap4 = (const uint4*)d_ap;

    int n = row + 1;
    int chunk = ((n + 255) >> 8) << 6;          // 64-aligned, 4*chunk >= n
    int cstart = warp * chunk;
    int cend   = min(cstart + chunk, n);

    int fj = 0x7fffffff;            // first v==8 column in this warp's chunk
    int best_v = -1, best_j = 0;    // per-lane best (ascending j per lane)

    for (int b = cstart; b < cend; b += 64) {
        int j1 = b + lane, j2 = j1 + 32;
        bool in1 = (j1 < cend), in2 = (j2 < cend);
        uint4 kk1, pp1, kk2, pp2;
        if (in1) { kk1 = ak4[j1]; pp1 = ap4[row - j1]; }
        if (in2) { kk2 = ak4[j2]; pp2 = ap4[row - j2]; }
        int v1 = -1, v2 = -1;
        if (in1) v1 = votes8(sbits, kk1, pp1, q0, q1, q2, q3, q4, q5, q6, q7);
        if (in2) v2 = votes8(sbits, kk2, pp2, q0, q1, q2, q3, q4, q5, q6, q7);

        unsigned m1 = __ballot_sync(0xffffffffu, v1 == HH);
        unsigned m2 = __ballot_sync(0xffffffffu, v2 == HH);
        if (m1 | m2) {
            // all j1 (b..b+31) precede all j2 (b+32..b+63)
            fj = m1 ? (b + __ffs(m1) - 1) : (b + 32 + __ffs(m2) - 1);
            break;
        }
        if (v1 > best_v) { best_v = v1; best_j = j1; }
        if (v2 > best_v) { best_v = v2; best_j = j2; }
    }

    // per-warp best key (max v, then min j): key = (v<<11) | (2047 - j)
    int key = (best_v << 11) | (2047 - best_j);
#pragma unroll
    for (int o = 16; o; o >>= 1) key = max(key, __shfl_xor_sync(0xffffffffu, key, o));
    if (lane == 0) { sfj[warp] = fj; skey[warp] = key; }
    __syncthreads();

    // Combine: chunks are ordered, each warp scanned its whole chunk.
    int bv, bj = -1;
#pragma unroll
    for (int w = 0; w < 4; w++)
        if (bj < 0 && sfj[w] != 0x7fffffff) bj = sfj[w];
    if (bj >= 0) {
        bv = HH;
    } else {
        int k = max(max(skey[0], skey[1]), max(skey[2], skey[3]));
        bv = k >> 11;
        bj = 2047 - (k & 2047);
    }

    // Output row (threads 0..63), block-uniform (bv, bj).
    if (tid < BB) {
        float r = 0.0f;
        if (bv > 0) {
            int a = d_addrv[bj * BB + tid];
            r = table_v[tid * 4096 + a];
        }
        out[row * BB + tid] = r;
    }
}

// ---------------------------------------------------------------------------
extern "C" void kernel_launch(void* const* d_in, const int* in_sizes, int n_in,
                              void* d_out, int out_size) {
    const int*   tokens     = (const int*)d_in[0];
    const int*   conn_heads = (const int*)d_in[1];
    const float* head_table = (const float*)d_in[2];
    const int*   conn_v     = (const int*)d_in[3];
    const float* table_v    = (const float*)d_in[4];
    float*       out        = (float*)d_out;

    prep_kernel<<<512, 256>>>(tokens, conn_heads, head_table, conn_v);
    scan_kernel<<<SS, 128>>>(table_v, out);
}